// round 13
// baseline (speedup 1.0000x reference)
#include <cuda_runtime.h>
#include <cstdint>

#define BB 8
#define CC 16
#define FDIM 256
#define F2 129
#define TT 512
#define C2 32
#define HH 16
#define NT (BB*TT)

// ---------------- device scratch ----------------
__device__ float g_zraw[(size_t)BB*C2*F2*TT];   // spectrum planes (b, c2, k, t): re c=0..15, im c=16..31
__device__ float g_pre [(size_t)NT*F2*128];     // gate preactivations (n, k, 128): [dir*64 + row]
__device__ float g_h   [(size_t)NT*F2*C2];      // LSTM hidden cat(fwd,bwd): (n, k, 2H)
__device__ float g_P   [(size_t)BB*C2*F2*TT];   // product spectrum planes
__device__ float g_mean[NT];
__device__ float g_rstd[NT];
__device__ float g_psum[NT*16];                 // 16 channel-partials per n (from fft_fwd)
__device__ float g_psq [NT*16];

__device__ __forceinline__ float sigf(float x) {
    return __fdividef(1.f, 1.f + __expf(-x));
}
__device__ __forceinline__ float tanhfast(float x) {
    return fmaf(2.f, __fdividef(1.f, 1.f + __expf(-2.f * x)), -1.f);
}
__device__ __forceinline__ unsigned int f2tf32(float f) {
    unsigned int r;
    asm("cvt.rna.tf32.f32 %0, %1;" : "=r"(r) : "f"(f));
    return r;
}
__device__ __forceinline__ void mma_tf32(float* d,
    unsigned int a0, unsigned int a1, unsigned int a2, unsigned int a3,
    unsigned int b0, unsigned int b1) {
    asm volatile(
        "mma.sync.aligned.m16n8k8.row.col.f32.tf32.tf32.f32 "
        "{%0,%1,%2,%3}, {%4,%5,%6,%7}, {%8,%9}, {%0,%1,%2,%3};"
        : "+f"(d[0]), "+f"(d[1]), "+f"(d[2]), "+f"(d[3])
        : "r"(a0), "r"(a1), "r"(a2), "r"(a3), "r"(b0), "r"(b1));
}
__device__ __forceinline__ int dr4(int k) {   // base-4 digit reversal, 4 digits
    return ((k & 3) << 6) | (((k >> 2) & 3) << 4) | (((k >> 4) & 3) << 2) | ((k >> 6) & 3);
}

// ---------------- K1: forward rfft + fused norm-stat partials ----------------
// grid (128, 16), block 512 (16 warps). 32 t-cols -> 16 complex FFTs, one/warp.
__global__ void __launch_bounds__(512) k_fft_fwd(const float* __restrict__ x) {
    int bc = blockIdx.x;
    int t0 = blockIdx.y * 32;
    int b = bc >> 4, c = bc & 15;
    __shared__ float sr[258][17], si[258][17];
    __shared__ float2 tw[192];
    int tid = threadIdx.x;
    int w = tid >> 5, l = tid & 31;

    if (tid < 192) {
        float sv, cv;
        __sincosf(-6.28318530717958647692f * (float)tid * (1.f / 256.f), &sv, &cv);
        tw[tid] = make_float2(cv, sv);
    }
    for (int i = tid; i < 8192; i += 512) {
        int f = i >> 5, tt = i & 31;
        float v = x[((size_t)bc * 256 + f) * 512 + t0 + tt];
        if (tt & 1) si[f][tt >> 1] = v; else sr[f][tt >> 1] = v;
    }
    __syncthreads();

    #pragma unroll
    for (int stage = 0; stage < 4; ++stage) {
        int ms = 6 - 2 * stage;
        int m = 1 << ms;
        #pragma unroll
        for (int half = 0; half < 2; ++half) {
            int bfy = l + 32 * half;
            int g = bfy >> ms, p = bfy & (m - 1);
            int base = (g << (ms + 2)) + p;
            int e1 = p << (2 * stage);
            float2 w1 = tw[e1], w2 = tw[2 * e1], w3 = tw[3 * e1];
            float ar = sr[base][w],        ai = si[base][w];
            float br = sr[base + m][w],    bi = si[base + m][w];
            float cr = sr[base + 2*m][w],  ci = si[base + 2*m][w];
            float dr = sr[base + 3*m][w],  di = si[base + 3*m][w];
            float t0r = ar + cr, t0i = ai + ci;
            float t1r = ar - cr, t1i = ai - ci;
            float t2r = br + dr, t2i = bi + di;
            float t3r = br - dr, t3i = bi - di;
            sr[base][w] = t0r + t2r;  si[base][w] = t0i + t2i;
            float u1r = t1r + t3i, u1i = t1i - t3r;
            sr[base + m][w]   = u1r * w1.x - u1i * w1.y;
            si[base + m][w]   = u1r * w1.y + u1i * w1.x;
            float v2r = t0r - t2r, v2i = t0i - t2i;
            sr[base + 2*m][w] = v2r * w2.x - v2i * w2.y;
            si[base + 2*m][w] = v2r * w2.y + v2i * w2.x;
            float u3r = t1r - t3i, u3i = t1i + t3r;
            sr[base + 3*m][w] = u3r * w3.x - u3i * w3.y;
            si[base + 3*m][w] = u3r * w3.y + u3i * w3.x;
        }
        __syncwarp();
    }

    float va[5][4];
    #pragma unroll
    for (int r = 0; r < 4; ++r) {
        int k = l + 32 * r;
        int ik = dr4(k), im = dr4((256 - k) & 255);
        float zkr = sr[ik][w], zki = si[ik][w];
        float zmr = sr[im][w], zmi = si[im][w];
        va[r][0] = 0.5f * (zkr + zmr);
        va[r][1] = 0.5f * (zki - zmi);
        va[r][2] = 0.5f * (zki + zmi);
        va[r][3] = 0.5f * (zmr - zkr);
    }
    if (l == 0) {
        int ik = dr4(128);
        float zkr = sr[ik][w], zki = si[ik][w];
        va[4][0] = zkr; va[4][1] = 0.f;
        va[4][2] = zki; va[4][3] = 0.f;
    }

    // fused stats partials
    {
        float sA = 0.f, qA = 0.f, sB = 0.f, qB = 0.f;
        #pragma unroll
        for (int r = 0; r < 4; ++r) {
            sA += va[r][0] + va[r][1];
            qA = fmaf(va[r][0], va[r][0], qA); qA = fmaf(va[r][1], va[r][1], qA);
            sB += va[r][2] + va[r][3];
            qB = fmaf(va[r][2], va[r][2], qB); qB = fmaf(va[r][3], va[r][3], qB);
        }
        if (l == 0) {
            sA += va[4][0] + va[4][1];
            qA = fmaf(va[4][0], va[4][0], qA); qA = fmaf(va[4][1], va[4][1], qA);
            sB += va[4][2] + va[4][3];
            qB = fmaf(va[4][2], va[4][2], qB); qB = fmaf(va[4][3], va[4][3], qB);
        }
        #pragma unroll
        for (int off = 16; off; off >>= 1) {
            sA += __shfl_xor_sync(0xffffffffu, sA, off);
            qA += __shfl_xor_sync(0xffffffffu, qA, off);
            sB += __shfl_xor_sync(0xffffffffu, sB, off);
            qB += __shfl_xor_sync(0xffffffffu, qB, off);
        }
        if (l == 0) {
            int nA = b * 512 + t0 + 2 * w;
            g_psum[nA * 16 + c] = sA;       g_psq[nA * 16 + c] = qA;
            g_psum[(nA + 1) * 16 + c] = sB; g_psq[(nA + 1) * 16 + c] = qB;
        }
    }

    __syncwarp();
    #pragma unroll
    for (int r = 0; r < 4; ++r) {
        int k = l + 32 * r;
        sr[k][w] = va[r][0];        si[k][w] = va[r][1];
        sr[129 + k][w] = va[r][2];  si[129 + k][w] = va[r][3];
    }
    if (l == 0) {
        sr[128][w] = va[4][0];       si[128][w] = va[4][1];
        sr[129 + 128][w] = va[4][2]; si[129 + 128][w] = va[4][3];
    }
    __syncthreads();

    for (int i = tid; i < 4128; i += 512) {
        int k = i >> 5, tt = i & 31;
        int j = tt >> 1;
        int row = (tt & 1) ? (129 + k) : k;
        g_zraw[(((size_t)b * 32 + c)      * 129 + k) * 512 + t0 + tt] = sr[row][j];
        g_zraw[(((size_t)b * 32 + 16 + c) * 129 + k) * 512 + t0 + tt] = si[row][j];
    }
}

// ---------------- K2: finalize stats (16 partials per n) --------------------
__global__ void k_stats2() {
    int n = blockIdx.x * 256 + threadIdx.x;
    float S = 0.f, Q = 0.f;
    #pragma unroll
    for (int p = 0; p < 16; ++p) { S += g_psum[n * 16 + p]; Q += g_psq[n * 16 + p]; }
    float mean = S * (1.f / 4128.f);
    float var = (Q - S * mean) * (1.f / 4127.f);
    g_mean[n] = mean;
    g_rstd[n] = __fdividef(1.f, sqrtf(fmaxf(var, 0.f)) + 1e-8f);
}

// ---------------- K3: normalize + input-gate GEMM via tf32 mma.sync ---------
__global__ void __launch_bounds__(256) k_gates(
    const float* __restrict__ nw, const float* __restrict__ nb,
    const float* __restrict__ wihf, const float* __restrict__ bihf, const float* __restrict__ bhhf,
    const float* __restrict__ wihb, const float* __restrict__ bihb, const float* __restrict__ bhhb) {
    int k = blockIdx.x;
    int n0 = blockIdx.y * 64;
    int b = n0 >> 9, tl0 = n0 & 511;
    __shared__ unsigned int ys[32][72];   // [q][t] tf32 bits after normalize
    __shared__ unsigned int ws[128][36];  // [gate][q] tf32 bits
    __shared__ float nws[32], nbs[32], means[64], rstds[64], bs[128];
    int tid = threadIdx.x;

    for (int i = tid; i < 2048; i += 256) {
        int c2 = i >> 6, tt = i & 63;
        ys[c2][tt] = __float_as_uint(g_zraw[(((size_t)b * 32 + c2) * 129 + k) * 512 + tl0 + tt]);
    }
    for (int i = tid; i < 4096; i += 256) {
        int g = i >> 5, q = i & 31;
        float wv = (g < 64) ? wihf[g * 32 + q] : wihb[(g - 64) * 32 + q];
        ws[g][q] = f2tf32(wv);
    }
    if (tid < 64) bs[tid] = bihf[tid] + bhhf[tid];
    else if (tid < 128) bs[tid] = bihb[tid - 64] + bhhb[tid - 64];
    if (tid < 32) { nws[tid] = nw[tid * 129 + k]; nbs[tid] = nb[tid * 129 + k]; }
    if (tid >= 128 && tid < 192) { means[tid - 128] = g_mean[n0 + tid - 128]; rstds[tid - 128] = g_rstd[n0 + tid - 128]; }
    __syncthreads();

    for (int i = tid; i < 2048; i += 256) {
        int c2 = i >> 6, tt = i & 63;
        float v = (__uint_as_float(ys[c2][tt]) - means[tt]) * rstds[tt] * nws[c2] + nbs[c2];
        ys[c2][tt] = f2tf32(v);
    }
    __syncthreads();

    int wid = tid >> 5, lane = tid & 31;
    int gid = lane >> 2, tid4 = lane & 3;
    int m_base = (wid & 3) << 4;
    int n_base0 = (wid >> 2) << 6;

    float acc[8][4];
    #pragma unroll
    for (int j = 0; j < 8; ++j) {
        int gb = n_base0 + j * 8 + tid4 * 2;
        acc[j][0] = bs[gb];     acc[j][1] = bs[gb + 1];
        acc[j][2] = bs[gb];     acc[j][3] = bs[gb + 1];
    }

    #pragma unroll
    for (int ks = 0; ks < 32; ks += 8) {
        unsigned int a0 = ys[ks + tid4    ][m_base + gid];
        unsigned int a1 = ys[ks + tid4    ][m_base + gid + 8];
        unsigned int a2 = ys[ks + tid4 + 4][m_base + gid];
        unsigned int a3 = ys[ks + tid4 + 4][m_base + gid + 8];
        #pragma unroll
        for (int j = 0; j < 8; ++j) {
            int gb = n_base0 + j * 8 + gid;
            unsigned int b0 = ws[gb][ks + tid4];
            unsigned int b1 = ws[gb][ks + tid4 + 4];
            mma_tf32(acc[j], a0, a1, a2, a3, b0, b1);
        }
    }

    #pragma unroll
    for (int j = 0; j < 8; ++j) {
        int gate = n_base0 + j * 8 + tid4 * 2;
        int trow = n0 + m_base + gid;
        float2 v0 = make_float2(acc[j][0], acc[j][1]);
        float2 v1 = make_float2(acc[j][2], acc[j][3]);
        *reinterpret_cast<float2*>(&g_pre[((size_t)trow * 129 + k) * 128 + gate]) = v0;
        *reinterpret_cast<float2*>(&g_pre[((size_t)(trow + 8) * 129 + k) * 128 + gate]) = v1;
    }
}

// ---------------- K4: LSTM, 2 sequences/warp, hidden-unit-per-lane ----------
// grid 512, block 256 (8 warps). Warp = (seq pair, dir). Lane j<16: seq A unit j,
// lane j+16: seq B unit j. Each lane computes all 4 gates of its unit locally.
__global__ void __launch_bounds__(256) k_lstm(
    const float* __restrict__ whhf, const float* __restrict__ whhb) {
    int wg = blockIdx.x * 8 + (threadIdx.x >> 5);   // 0..4095
    int lane = threadIdx.x & 31;
    int j = lane & 15;                // hidden unit
    int half = lane >> 4;             // which seq of the pair
    int pair = wg >> 1, dir = wg & 1;
    int n = pair * 2 + half;

    const float* whh = dir ? whhb : whhf;
    // lane j owns gate rows j, j+16, j+32, j+48 (i,f,g,o of unit j)
    float wv[4][16];
    #pragma unroll
    for (int t = 0; t < 4; ++t)
        #pragma unroll
        for (int q = 0; q < 16; ++q)
            wv[t][q] = whh[(t * 16 + j) * 16 + q];

    const float* pbase = g_pre + (size_t)n * 129 * 128 + dir * 64 + j;
    float* hbase = g_h + (size_t)n * 129 * 32 + dir * 16 + j;
    int base16 = lane & 16;

    float h = 0.f, cst = 0.f;
    int k = dir ? 128 : 0;
    int stepd = dir ? -1 : 1;
    float p0 = pbase[k * 128];
    float p1 = pbase[k * 128 + 16];
    float p2 = pbase[k * 128 + 32];
    float p3 = pbase[k * 128 + 48];

    for (int s = 0; s < 129; ++s) {
        int kn = k + stepd;
        float np0 = 0.f, np1 = 0.f, np2 = 0.f, np3 = 0.f;
        if (s < 128) {
            np0 = pbase[kn * 128];
            np1 = pbase[kn * 128 + 16];
            np2 = pbase[kn * 128 + 32];
            np3 = pbase[kn * 128 + 48];
        }
        float a0 = p0, a1 = p1, a2 = p2, a3 = p3;
        #pragma unroll
        for (int q = 0; q < 16; ++q) {
            float hv = __shfl_sync(0xffffffffu, h, base16 + q);
            a0 = fmaf(hv, wv[0][q], a0);
            a1 = fmaf(hv, wv[1][q], a1);
            a2 = fmaf(hv, wv[2][q], a2);
            a3 = fmaf(hv, wv[3][q], a3);
        }
        float ig = sigf(a0);
        float ff = sigf(a1);
        float gg = tanhfast(a2);
        float oo = sigf(a3);
        cst = fmaf(ff, cst, ig * gg);
        h = oo * tanhfast(cst);
        hbase[k * 32] = h;
        p0 = np0; p1 = np1; p2 = np2; p3 = np3; k = kn;
    }
}

// ---------------- K5: linear(2H->2C) + complex multiply ---------------------
__global__ void k_lin_cmul(const float* __restrict__ lw, const float* __restrict__ lb) {
    int k = blockIdx.x, t0 = blockIdx.y * 32, b = blockIdx.z;
    __shared__ float hs[32][33];    // [t][j]
    __shared__ float lws[32][32];   // [c2][j]
    __shared__ float lbs[32];
    __shared__ float yls[32][33];   // [c2][t]
    int tid = threadIdx.x;

    for (int i = tid; i < 1024; i += 256) lws[i >> 5][i & 31] = lw[i];
    if (tid < 32) lbs[tid] = lb[tid];
    for (int i = tid; i < 1024; i += 256) {
        int tt = i >> 5, j = i & 31;
        hs[tt][j] = g_h[(((size_t)(b * 512 + t0 + tt)) * 129 + k) * 32 + j];
    }
    __syncthreads();

    int tt = tid & 31, g = tid >> 5;
    #pragma unroll
    for (int ci = 0; ci < 4; ++ci) {
        int c2 = g + ci * 8;
        float acc = lbs[c2];
        #pragma unroll
        for (int j = 0; j < 32; ++j) acc = fmaf(hs[tt][j], lws[c2][j], acc);
        yls[c2][tt] = acc;
    }
    __syncthreads();

    size_t basez = ((size_t)(b * 32) * 129 + k) * 512 + t0 + tt;
    const size_t ps = (size_t)129 * 512;
    #pragma unroll
    for (int ci = 0; ci < 4; ++ci) {
        int c2 = g + ci * 8;
        if (c2 < 16) {
            float xr = g_zraw[basez + (size_t)c2 * ps];
            float xi = g_zraw[basez + (size_t)(c2 + 16) * ps];
            float yr = yls[c2][tt], yi = yls[c2 + 16][tt];
            g_P[basez + (size_t)c2 * ps] = yr * xr - yi * xi;
        } else {
            int c = c2 - 16;
            float xr = g_zraw[basez + (size_t)c * ps];
            float xi = g_zraw[basez + (size_t)c2 * ps];
            float yr = yls[c][tt], yi = yls[c2][tt];
            g_P[basez + (size_t)c2 * ps] = yr * xi + yi * xr;
        }
    }
}

// ---------------- K6: irfft, warp-private radix-4, spectrum-pair packed -----
__global__ void __launch_bounds__(512) k_fft_inv(float* __restrict__ out) {
    int bc = blockIdx.x;
    int t0 = blockIdx.y * 32;
    int b = bc >> 4, c = bc & 15;
    __shared__ float sr[258][17], si[258][17];
    __shared__ float2 tw[192];
    int tid = threadIdx.x;
    int w = tid >> 5, l = tid & 31;

    if (tid < 192) {
        float sv, cv;
        __sincosf(6.28318530717958647692f * (float)tid * (1.f / 256.f), &sv, &cv);
        tw[tid] = make_float2(cv, sv);
    }
    for (int i = tid; i < 4128; i += 512) {
        int k = i >> 5, tt = i & 31;
        int j = tt >> 1;
        int row = (tt & 1) ? (129 + k) : k;
        sr[row][j] = g_P[(((size_t)b * 32 + c)      * 129 + k) * 512 + t0 + tt];
        si[row][j] = g_P[(((size_t)b * 32 + 16 + c) * 129 + k) * 512 + t0 + tt];
    }
    __syncthreads();

    float vz[8][2];
    #pragma unroll
    for (int r = 0; r < 8; ++r) {
        int row = l + 32 * r;
        float zr, zi;
        if (row <= 128) {
            float par = sr[row][w];
            float pai = (row == 0 || row == 128) ? 0.f : si[row][w];
            float pbr = sr[129 + row][w];
            float pbi = (row == 0 || row == 128) ? 0.f : si[129 + row][w];
            zr = par - pbi; zi = pai + pbr;
        } else {
            int m = 256 - row;
            float par = sr[m][w], pai = si[m][w];
            float pbr = sr[129 + m][w], pbi = si[129 + m][w];
            zr = par + pbi; zi = pbr - pai;
        }
        vz[r][0] = zr; vz[r][1] = zi;
    }
    __syncwarp();
    #pragma unroll
    for (int r = 0; r < 8; ++r) {
        int row = l + 32 * r;
        sr[row][w] = vz[r][0];
        si[row][w] = vz[r][1];
    }
    __syncwarp();

    #pragma unroll
    for (int stage = 0; stage < 4; ++stage) {
        int ms = 6 - 2 * stage;
        int m = 1 << ms;
        #pragma unroll
        for (int half = 0; half < 2; ++half) {
            int bfy = l + 32 * half;
            int g = bfy >> ms, p = bfy & (m - 1);
            int base = (g << (ms + 2)) + p;
            int e1 = p << (2 * stage);
            float2 w1 = tw[e1], w2 = tw[2 * e1], w3 = tw[3 * e1];
            float ar = sr[base][w],        ai = si[base][w];
            float br = sr[base + m][w],    bi = si[base + m][w];
            float cr = sr[base + 2*m][w],  ci = si[base + 2*m][w];
            float dr = sr[base + 3*m][w],  di = si[base + 3*m][w];
            float t0r = ar + cr, t0i = ai + ci;
            float t1r = ar - cr, t1i = ai - ci;
            float t2r = br + dr, t2i = bi + di;
            float t3r = br - dr, t3i = bi - di;
            sr[base][w] = t0r + t2r;  si[base][w] = t0i + t2i;
            float u1r = t1r - t3i, u1i = t1i + t3r;
            sr[base + m][w]   = u1r * w1.x - u1i * w1.y;
            si[base + m][w]   = u1r * w1.y + u1i * w1.x;
            float v2r = t0r - t2r, v2i = t0i - t2i;
            sr[base + 2*m][w] = v2r * w2.x - v2i * w2.y;
            si[base + 2*m][w] = v2r * w2.y + v2i * w2.x;
            float u3r = t1r + t3i, u3i = t1i - t3r;
            sr[base + 3*m][w] = u3r * w3.x - u3i * w3.y;
            si[base + 3*m][w] = u3r * w3.y + u3i * w3.x;
        }
        __syncwarp();
    }
    __syncthreads();

    const float inv = 1.f / 256.f;
    for (int i = tid; i < 8192; i += 512) {
        int f = i >> 5, tt = i & 31;
        int j = tt >> 1;
        int src = dr4(f);
        float v = (tt & 1) ? si[src][j] : sr[src][j];
        out[((size_t)bc * 256 + f) * 512 + t0 + tt] = v * inv;
    }
}

// ---------------- launcher ---------------------------------------------------
extern "C" void kernel_launch(void* const* d_in, const int* in_sizes, int n_in,
                              void* d_out, int out_size) {
    const float* x    = (const float*)d_in[0];
    const float* nw   = (const float*)d_in[1];
    const float* nb   = (const float*)d_in[2];
    const float* wihf = (const float*)d_in[3];
    const float* whhf = (const float*)d_in[4];
    const float* bihf = (const float*)d_in[5];
    const float* bhhf = (const float*)d_in[6];
    const float* wihb = (const float*)d_in[7];
    const float* whhb = (const float*)d_in[8];
    const float* bihb = (const float*)d_in[9];
    const float* bhhb = (const float*)d_in[10];
    const float* lw   = (const float*)d_in[11];
    const float* lb   = (const float*)d_in[12];
    float* out = (float*)d_out;

    k_fft_fwd<<<dim3(128, 16), 512>>>(x);
    k_stats2<<<16, 256>>>();
    k_gates<<<dim3(129, 64), 256>>>(nw, nb, wihf, bihf, bhhf, wihb, bihb, bhhb);
    k_lstm<<<512, 256>>>(whhf, whhb);
    k_lin_cmul<<<dim3(129, 16, 8), 256>>>(lw, lb);
    k_fft_inv<<<dim3(128, 16), 512>>>(out);
}

// round 14
// speedup vs baseline: 1.0567x; 1.0567x over previous
#include <cuda_runtime.h>
#include <cstdint>

#define BB 8
#define CC 16
#define FDIM 256
#define F2 129
#define TT 512
#define C2 32
#define HH 16
#define NT (BB*TT)

// ---------------- device scratch ----------------
__device__ float g_zraw[(size_t)BB*C2*F2*TT];   // spectrum planes (b, c2, k, t): re c=0..15, im c=16..31
__device__ float g_pre [(size_t)NT*F2*128];     // gate preactivations (n, k, 128): [dir*64 + row]
__device__ float g_h   [(size_t)NT*F2*C2];      // LSTM hidden cat(fwd,bwd): (n, k, 2H)
__device__ float g_P   [(size_t)BB*C2*F2*TT];   // product spectrum planes
__device__ float g_mean[NT];
__device__ float g_rstd[NT];
__device__ float g_psum[NT*16];                 // 16 channel-partials per n (from fft_fwd)
__device__ float g_psq [NT*16];

__device__ __forceinline__ float sigf(float x) {
    return __fdividef(1.f, 1.f + __expf(-x));
}
__device__ __forceinline__ float tanhfast(float x) {
    return fmaf(2.f, __fdividef(1.f, 1.f + __expf(-2.f * x)), -1.f);
}
__device__ __forceinline__ unsigned int f2tf32(float f) {
    unsigned int r;
    asm("cvt.rna.tf32.f32 %0, %1;" : "=r"(r) : "f"(f));
    return r;
}
__device__ __forceinline__ void mma_tf32(float* d,
    unsigned int a0, unsigned int a1, unsigned int a2, unsigned int a3,
    unsigned int b0, unsigned int b1) {
    asm volatile(
        "mma.sync.aligned.m16n8k8.row.col.f32.tf32.tf32.f32 "
        "{%0,%1,%2,%3}, {%4,%5,%6,%7}, {%8,%9}, {%0,%1,%2,%3};"
        : "+f"(d[0]), "+f"(d[1]), "+f"(d[2]), "+f"(d[3])
        : "r"(a0), "r"(a1), "r"(a2), "r"(a3), "r"(b0), "r"(b1));
}
__device__ __forceinline__ int dr4(int k) {   // base-4 digit reversal, 4 digits
    return ((k & 3) << 6) | (((k >> 2) & 3) << 4) | (((k >> 4) & 3) << 2) | ((k >> 6) & 3);
}

// ---------------- K1: forward rfft + fused norm-stat partials ----------------
// grid (128, 16), block 512 (16 warps). 32 t-cols -> 16 complex FFTs, one/warp.
__global__ void __launch_bounds__(512) k_fft_fwd(const float* __restrict__ x) {
    int bc = blockIdx.x;
    int t0 = blockIdx.y * 32;
    int b = bc >> 4, c = bc & 15;
    __shared__ float sr[258][17], si[258][17];
    __shared__ float2 tw[192];
    int tid = threadIdx.x;
    int w = tid >> 5, l = tid & 31;

    if (tid < 192) {
        float sv, cv;
        __sincosf(-6.28318530717958647692f * (float)tid * (1.f / 256.f), &sv, &cv);
        tw[tid] = make_float2(cv, sv);
    }
    for (int i = tid; i < 8192; i += 512) {
        int f = i >> 5, tt = i & 31;
        float v = x[((size_t)bc * 256 + f) * 512 + t0 + tt];
        if (tt & 1) si[f][tt >> 1] = v; else sr[f][tt >> 1] = v;
    }
    __syncthreads();

    #pragma unroll
    for (int stage = 0; stage < 4; ++stage) {
        int ms = 6 - 2 * stage;
        int m = 1 << ms;
        #pragma unroll
        for (int half = 0; half < 2; ++half) {
            int bfy = l + 32 * half;
            int g = bfy >> ms, p = bfy & (m - 1);
            int base = (g << (ms + 2)) + p;
            int e1 = p << (2 * stage);
            float2 w1 = tw[e1], w2 = tw[2 * e1], w3 = tw[3 * e1];
            float ar = sr[base][w],        ai = si[base][w];
            float br = sr[base + m][w],    bi = si[base + m][w];
            float cr = sr[base + 2*m][w],  ci = si[base + 2*m][w];
            float dr = sr[base + 3*m][w],  di = si[base + 3*m][w];
            float t0r = ar + cr, t0i = ai + ci;
            float t1r = ar - cr, t1i = ai - ci;
            float t2r = br + dr, t2i = bi + di;
            float t3r = br - dr, t3i = bi - di;
            sr[base][w] = t0r + t2r;  si[base][w] = t0i + t2i;
            float u1r = t1r + t3i, u1i = t1i - t3r;
            sr[base + m][w]   = u1r * w1.x - u1i * w1.y;
            si[base + m][w]   = u1r * w1.y + u1i * w1.x;
            float v2r = t0r - t2r, v2i = t0i - t2i;
            sr[base + 2*m][w] = v2r * w2.x - v2i * w2.y;
            si[base + 2*m][w] = v2r * w2.y + v2i * w2.x;
            float u3r = t1r - t3i, u3i = t1i + t3r;
            sr[base + 3*m][w] = u3r * w3.x - u3i * w3.y;
            si[base + 3*m][w] = u3r * w3.y + u3i * w3.x;
        }
        __syncwarp();
    }

    float va[5][4];
    #pragma unroll
    for (int r = 0; r < 4; ++r) {
        int k = l + 32 * r;
        int ik = dr4(k), im = dr4((256 - k) & 255);
        float zkr = sr[ik][w], zki = si[ik][w];
        float zmr = sr[im][w], zmi = si[im][w];
        va[r][0] = 0.5f * (zkr + zmr);
        va[r][1] = 0.5f * (zki - zmi);
        va[r][2] = 0.5f * (zki + zmi);
        va[r][3] = 0.5f * (zmr - zkr);
    }
    if (l == 0) {
        int ik = dr4(128);
        float zkr = sr[ik][w], zki = si[ik][w];
        va[4][0] = zkr; va[4][1] = 0.f;
        va[4][2] = zki; va[4][3] = 0.f;
    }

    // fused stats partials
    {
        float sA = 0.f, qA = 0.f, sB = 0.f, qB = 0.f;
        #pragma unroll
        for (int r = 0; r < 4; ++r) {
            sA += va[r][0] + va[r][1];
            qA = fmaf(va[r][0], va[r][0], qA); qA = fmaf(va[r][1], va[r][1], qA);
            sB += va[r][2] + va[r][3];
            qB = fmaf(va[r][2], va[r][2], qB); qB = fmaf(va[r][3], va[r][3], qB);
        }
        if (l == 0) {
            sA += va[4][0] + va[4][1];
            qA = fmaf(va[4][0], va[4][0], qA); qA = fmaf(va[4][1], va[4][1], qA);
            sB += va[4][2] + va[4][3];
            qB = fmaf(va[4][2], va[4][2], qB); qB = fmaf(va[4][3], va[4][3], qB);
        }
        #pragma unroll
        for (int off = 16; off; off >>= 1) {
            sA += __shfl_xor_sync(0xffffffffu, sA, off);
            qA += __shfl_xor_sync(0xffffffffu, qA, off);
            sB += __shfl_xor_sync(0xffffffffu, sB, off);
            qB += __shfl_xor_sync(0xffffffffu, qB, off);
        }
        if (l == 0) {
            int nA = b * 512 + t0 + 2 * w;
            g_psum[nA * 16 + c] = sA;       g_psq[nA * 16 + c] = qA;
            g_psum[(nA + 1) * 16 + c] = sB; g_psq[(nA + 1) * 16 + c] = qB;
        }
    }

    __syncwarp();
    #pragma unroll
    for (int r = 0; r < 4; ++r) {
        int k = l + 32 * r;
        sr[k][w] = va[r][0];        si[k][w] = va[r][1];
        sr[129 + k][w] = va[r][2];  si[129 + k][w] = va[r][3];
    }
    if (l == 0) {
        sr[128][w] = va[4][0];       si[128][w] = va[4][1];
        sr[129 + 128][w] = va[4][2]; si[129 + 128][w] = va[4][3];
    }
    __syncthreads();

    for (int i = tid; i < 4128; i += 512) {
        int k = i >> 5, tt = i & 31;
        int j = tt >> 1;
        int row = (tt & 1) ? (129 + k) : k;
        g_zraw[(((size_t)b * 32 + c)      * 129 + k) * 512 + t0 + tt] = sr[row][j];
        g_zraw[(((size_t)b * 32 + 16 + c) * 129 + k) * 512 + t0 + tt] = si[row][j];
    }
}

// ---------------- K2: finalize stats (16 partials per n) --------------------
__global__ void k_stats2() {
    int n = blockIdx.x * 256 + threadIdx.x;
    float S = 0.f, Q = 0.f;
    #pragma unroll
    for (int p = 0; p < 16; ++p) { S += g_psum[n * 16 + p]; Q += g_psq[n * 16 + p]; }
    float mean = S * (1.f / 4128.f);
    float var = (Q - S * mean) * (1.f / 4127.f);
    g_mean[n] = mean;
    g_rstd[n] = __fdividef(1.f, sqrtf(fmaxf(var, 0.f)) + 1e-8f);
}

// ---------------- K3: normalize + input-gate GEMM via tf32 mma.sync ---------
__global__ void __launch_bounds__(256) k_gates(
    const float* __restrict__ nw, const float* __restrict__ nb,
    const float* __restrict__ wihf, const float* __restrict__ bihf, const float* __restrict__ bhhf,
    const float* __restrict__ wihb, const float* __restrict__ bihb, const float* __restrict__ bhhb) {
    int k = blockIdx.x;
    int n0 = blockIdx.y * 64;
    int b = n0 >> 9, tl0 = n0 & 511;
    __shared__ unsigned int ys[32][72];   // [q][t] tf32 bits after normalize
    __shared__ unsigned int ws[128][36];  // [gate][q] tf32 bits
    __shared__ float nws[32], nbs[32], means[64], rstds[64], bs[128];
    int tid = threadIdx.x;

    for (int i = tid; i < 2048; i += 256) {
        int c2 = i >> 6, tt = i & 63;
        ys[c2][tt] = __float_as_uint(g_zraw[(((size_t)b * 32 + c2) * 129 + k) * 512 + tl0 + tt]);
    }
    for (int i = tid; i < 4096; i += 256) {
        int g = i >> 5, q = i & 31;
        float wv = (g < 64) ? wihf[g * 32 + q] : wihb[(g - 64) * 32 + q];
        ws[g][q] = f2tf32(wv);
    }
    if (tid < 64) bs[tid] = bihf[tid] + bhhf[tid];
    else if (tid < 128) bs[tid] = bihb[tid - 64] + bhhb[tid - 64];
    if (tid < 32) { nws[tid] = nw[tid * 129 + k]; nbs[tid] = nb[tid * 129 + k]; }
    if (tid >= 128 && tid < 192) { means[tid - 128] = g_mean[n0 + tid - 128]; rstds[tid - 128] = g_rstd[n0 + tid - 128]; }
    __syncthreads();

    for (int i = tid; i < 2048; i += 256) {
        int c2 = i >> 6, tt = i & 63;
        float v = (__uint_as_float(ys[c2][tt]) - means[tt]) * rstds[tt] * nws[c2] + nbs[c2];
        ys[c2][tt] = f2tf32(v);
    }
    __syncthreads();

    int wid = tid >> 5, lane = tid & 31;
    int gid = lane >> 2, tid4 = lane & 3;
    int m_base = (wid & 3) << 4;
    int n_base0 = (wid >> 2) << 6;

    float acc[8][4];
    #pragma unroll
    for (int j = 0; j < 8; ++j) {
        int gb = n_base0 + j * 8 + tid4 * 2;
        acc[j][0] = bs[gb];     acc[j][1] = bs[gb + 1];
        acc[j][2] = bs[gb];     acc[j][3] = bs[gb + 1];
    }

    #pragma unroll
    for (int ks = 0; ks < 32; ks += 8) {
        unsigned int a0 = ys[ks + tid4    ][m_base + gid];
        unsigned int a1 = ys[ks + tid4    ][m_base + gid + 8];
        unsigned int a2 = ys[ks + tid4 + 4][m_base + gid];
        unsigned int a3 = ys[ks + tid4 + 4][m_base + gid + 8];
        #pragma unroll
        for (int j = 0; j < 8; ++j) {
            int gb = n_base0 + j * 8 + gid;
            unsigned int b0 = ws[gb][ks + tid4];
            unsigned int b1 = ws[gb][ks + tid4 + 4];
            mma_tf32(acc[j], a0, a1, a2, a3, b0, b1);
        }
    }

    #pragma unroll
    for (int j = 0; j < 8; ++j) {
        int gate = n_base0 + j * 8 + tid4 * 2;
        int trow = n0 + m_base + gid;
        float2 v0 = make_float2(acc[j][0], acc[j][1]);
        float2 v1 = make_float2(acc[j][2], acc[j][3]);
        *reinterpret_cast<float2*>(&g_pre[((size_t)trow * 129 + k) * 128 + gate]) = v0;
        *reinterpret_cast<float2*>(&g_pre[((size_t)(trow + 8) * 129 + k) * 128 + gate]) = v1;
    }
}

// ---------------- K4: recurrent-only LSTM (R12 layout + split activations) --
// One warp per (seq, dir). Lane m<16: gates i_m, g_m; lane m+16: f_m, o_m.
// Each half activates its own gates; exchange ACTIVATED values via 2 shfl_xor.
__global__ void __launch_bounds__(256) k_lstm(
    const float* __restrict__ whhf, const float* __restrict__ whhb) {
    int wg = blockIdx.x * 8 + (threadIdx.x >> 5);
    int lane = threadIdx.x & 31;
    int n = wg >> 1, dir = wg & 1;

    const float* whh = dir ? whhb : whhf;
    float wh0[16], wh1[16];
    #pragma unroll
    for (int q = 0; q < 16; ++q) {
        wh0[q] = whh[lane * 16 + q];
        wh1[q] = whh[(lane + 32) * 16 + q];
    }
    // activation-select constants: lane<16 -> act1 = tanh (m2=2, mb=-1);
    //                              lane>=16 -> act1 = sigmoid (m2=1, mb=0)
    float m2 = (lane < 16) ? 2.f : 1.f;
    float mb = (lane < 16) ? -1.f : 0.f;

    const float* pbase = g_pre + (size_t)n * 129 * 128 + dir * 64;
    float* hbase = g_h + (size_t)n * 129 * 32 + dir * 16;

    float h = 0.f, cst = 0.f;
    int k = dir ? 128 : 0;
    int stepd = dir ? -1 : 1;
    float p0 = pbase[k * 128 + lane];
    float p1 = pbase[k * 128 + 32 + lane];

    #pragma unroll 2
    for (int s = 0; s < 129; ++s) {
        int kn = k + stepd;
        float np0, np1;
        if (s < 128) {   // predicated loads; last step reuses nothing
            np0 = pbase[kn * 128 + lane];
            np1 = pbase[kn * 128 + 32 + lane];
        } else { np0 = 0.f; np1 = 0.f; }
        float a0 = p0, a1 = p1, c0 = 0.f, c1 = 0.f;
        #pragma unroll
        for (int q = 0; q < 8; ++q) {
            float hv = __shfl_sync(0xffffffffu, h, q);
            a0 = fmaf(hv, wh0[q], a0);
            a1 = fmaf(hv, wh1[q], a1);
        }
        #pragma unroll
        for (int q = 8; q < 16; ++q) {
            float hv = __shfl_sync(0xffffffffu, h, q);
            c0 = fmaf(hv, wh0[q], c0);
            c1 = fmaf(hv, wh1[q], c1);
        }
        a0 += c0; a1 += c1;
        // all lanes: act0 = sigmoid(a0); act1 = tanh(a1) [lane<16] / sigmoid(a1)
        float act0 = sigf(a0);
        float r1 = __fdividef(1.f, 1.f + __expf(-m2 * a1));
        float act1 = fmaf(m2, r1, mb);
        float fa = __shfl_xor_sync(0xffffffffu, act0, 16);   // lane<16: sig(f)
        float oa = __shfl_xor_sync(0xffffffffu, act1, 16);   // lane<16: sig(o)
        if (lane < 16) {
            cst = fmaf(fa, cst, act0 * act1);
            h = oa * tanhfast(cst);
            hbase[k * 32 + lane] = h;
        }
        p0 = np0; p1 = np1; k = kn;
    }
}

// ---------------- K5: linear(2H->2C) + complex multiply ---------------------
__global__ void k_lin_cmul(const float* __restrict__ lw, const float* __restrict__ lb) {
    int k = blockIdx.x, t0 = blockIdx.y * 32, b = blockIdx.z;
    __shared__ float hs[32][33];    // [t][j]
    __shared__ float lws[32][32];   // [c2][j]
    __shared__ float lbs[32];
    __shared__ float yls[32][33];   // [c2][t]
    int tid = threadIdx.x;

    for (int i = tid; i < 1024; i += 256) lws[i >> 5][i & 31] = lw[i];
    if (tid < 32) lbs[tid] = lb[tid];
    for (int i = tid; i < 1024; i += 256) {
        int tt = i >> 5, j = i & 31;
        hs[tt][j] = g_h[(((size_t)(b * 512 + t0 + tt)) * 129 + k) * 32 + j];
    }
    __syncthreads();

    int tt = tid & 31, g = tid >> 5;
    #pragma unroll
    for (int ci = 0; ci < 4; ++ci) {
        int c2 = g + ci * 8;
        float acc = lbs[c2];
        #pragma unroll
        for (int j = 0; j < 32; ++j) acc = fmaf(hs[tt][j], lws[c2][j], acc);
        yls[c2][tt] = acc;
    }
    __syncthreads();

    size_t basez = ((size_t)(b * 32) * 129 + k) * 512 + t0 + tt;
    const size_t ps = (size_t)129 * 512;
    #pragma unroll
    for (int ci = 0; ci < 4; ++ci) {
        int c2 = g + ci * 8;
        if (c2 < 16) {
            float xr = g_zraw[basez + (size_t)c2 * ps];
            float xi = g_zraw[basez + (size_t)(c2 + 16) * ps];
            float yr = yls[c2][tt], yi = yls[c2 + 16][tt];
            g_P[basez + (size_t)c2 * ps] = yr * xr - yi * xi;
        } else {
            int c = c2 - 16;
            float xr = g_zraw[basez + (size_t)c * ps];
            float xi = g_zraw[basez + (size_t)c2 * ps];
            float yr = yls[c][tt], yi = yls[c2][tt];
            g_P[basez + (size_t)c2 * ps] = yr * xi + yi * xr;
        }
    }
}

// ---------------- K6: irfft, warp-private radix-4, spectrum-pair packed -----
__global__ void __launch_bounds__(512) k_fft_inv(float* __restrict__ out) {
    int bc = blockIdx.x;
    int t0 = blockIdx.y * 32;
    int b = bc >> 4, c = bc & 15;
    __shared__ float sr[258][17], si[258][17];
    __shared__ float2 tw[192];
    int tid = threadIdx.x;
    int w = tid >> 5, l = tid & 31;

    if (tid < 192) {
        float sv, cv;
        __sincosf(6.28318530717958647692f * (float)tid * (1.f / 256.f), &sv, &cv);
        tw[tid] = make_float2(cv, sv);
    }
    for (int i = tid; i < 4128; i += 512) {
        int k = i >> 5, tt = i & 31;
        int j = tt >> 1;
        int row = (tt & 1) ? (129 + k) : k;
        sr[row][j] = g_P[(((size_t)b * 32 + c)      * 129 + k) * 512 + t0 + tt];
        si[row][j] = g_P[(((size_t)b * 32 + 16 + c) * 129 + k) * 512 + t0 + tt];
    }
    __syncthreads();

    float vz[8][2];
    #pragma unroll
    for (int r = 0; r < 8; ++r) {
        int row = l + 32 * r;
        float zr, zi;
        if (row <= 128) {
            float par = sr[row][w];
            float pai = (row == 0 || row == 128) ? 0.f : si[row][w];
            float pbr = sr[129 + row][w];
            float pbi = (row == 0 || row == 128) ? 0.f : si[129 + row][w];
            zr = par - pbi; zi = pai + pbr;
        } else {
            int m = 256 - row;
            float par = sr[m][w], pai = si[m][w];
            float pbr = sr[129 + m][w], pbi = si[129 + m][w];
            zr = par + pbi; zi = pbr - pai;
        }
        vz[r][0] = zr; vz[r][1] = zi;
    }
    __syncwarp();
    #pragma unroll
    for (int r = 0; r < 8; ++r) {
        int row = l + 32 * r;
        sr[row][w] = vz[r][0];
        si[row][w] = vz[r][1];
    }
    __syncwarp();

    #pragma unroll
    for (int stage = 0; stage < 4; ++stage) {
        int ms = 6 - 2 * stage;
        int m = 1 << ms;
        #pragma unroll
        for (int half = 0; half < 2; ++half) {
            int bfy = l + 32 * half;
            int g = bfy >> ms, p = bfy & (m - 1);
            int base = (g << (ms + 2)) + p;
            int e1 = p << (2 * stage);
            float2 w1 = tw[e1], w2 = tw[2 * e1], w3 = tw[3 * e1];
            float ar = sr[base][w],        ai = si[base][w];
            float br = sr[base + m][w],    bi = si[base + m][w];
            float cr = sr[base + 2*m][w],  ci = si[base + 2*m][w];
            float dr = sr[base + 3*m][w],  di = si[base + 3*m][w];
            float t0r = ar + cr, t0i = ai + ci;
            float t1r = ar - cr, t1i = ai - ci;
            float t2r = br + dr, t2i = bi + di;
            float t3r = br - dr, t3i = bi - di;
            sr[base][w] = t0r + t2r;  si[base][w] = t0i + t2i;
            float u1r = t1r - t3i, u1i = t1i + t3r;
            sr[base + m][w]   = u1r * w1.x - u1i * w1.y;
            si[base + m][w]   = u1r * w1.y + u1i * w1.x;
            float v2r = t0r - t2r, v2i = t0i - t2i;
            sr[base + 2*m][w] = v2r * w2.x - v2i * w2.y;
            si[base + 2*m][w] = v2r * w2.y + v2i * w2.x;
            float u3r = t1r + t3i, u3i = t1i - t3r;
            sr[base + 3*m][w] = u3r * w3.x - u3i * w3.y;
            si[base + 3*m][w] = u3r * w3.y + u3i * w3.x;
        }
        __syncwarp();
    }
    __syncthreads();

    const float inv = 1.f / 256.f;
    for (int i = tid; i < 8192; i += 512) {
        int f = i >> 5, tt = i & 31;
        int j = tt >> 1;
        int src = dr4(f);
        float v = (tt & 1) ? si[src][j] : sr[src][j];
        out[((size_t)bc * 256 + f) * 512 + t0 + tt] = v * inv;
    }
}

// ---------------- launcher ---------------------------------------------------
extern "C" void kernel_launch(void* const* d_in, const int* in_sizes, int n_in,
                              void* d_out, int out_size) {
    const float* x    = (const float*)d_in[0];
    const float* nw   = (const float*)d_in[1];
    const float* nb   = (const float*)d_in[2];
    const float* wihf = (const float*)d_in[3];
    const float* whhf = (const float*)d_in[4];
    const float* bihf = (const float*)d_in[5];
    const float* bhhf = (const float*)d_in[6];
    const float* wihb = (const float*)d_in[7];
    const float* whhb = (const float*)d_in[8];
    const float* bihb = (const float*)d_in[9];
    const float* bhhb = (const float*)d_in[10];
    const float* lw   = (const float*)d_in[11];
    const float* lb   = (const float*)d_in[12];
    float* out = (float*)d_out;

    k_fft_fwd<<<dim3(128, 16), 512>>>(x);
    k_stats2<<<16, 256>>>();
    k_gates<<<dim3(129, 64), 256>>>(nw, nb, wihf, bihf, bhhf, wihb, bihb, bhhb);
    k_lstm<<<1024, 256>>>(whhf, whhb);
    k_lin_cmul<<<dim3(129, 16, 8), 256>>>(lw, lb);
    k_fft_inv<<<dim3(128, 16), 512>>>(out);
}

// round 15
// speedup vs baseline: 1.1741x; 1.1112x over previous
#include <cuda_runtime.h>
#include <cuda_fp16.h>
#include <cstdint>

#define BB 8
#define CC 16
#define FDIM 256
#define F2 129
#define TT 512
#define C2 32
#define HH 16
#define NT (BB*TT)

// ---------------- device scratch ----------------
__device__ float g_zraw[(size_t)BB*C2*F2*TT];   // spectrum planes (b, c2, k, t): re c=0..15, im c=16..31
__device__ __half g_pre16[(size_t)NT*F2*128];   // fp16 gate preacts, PERMUTED: pos 2m/2m+1 = rows m/m+32 per dir
__device__ float g_h   [(size_t)NT*F2*C2];      // LSTM hidden cat(fwd,bwd): (n, k, 2H)
__device__ float g_P   [(size_t)BB*C2*F2*TT];   // product spectrum planes
__device__ float g_mean[NT];
__device__ float g_rstd[NT];
__device__ float g_psum[NT*16];
__device__ float g_psq [NT*16];

__device__ __forceinline__ float sigf(float x) {
    return __fdividef(1.f, 1.f + __expf(-x));
}
__device__ __forceinline__ float tanhfast(float x) {
    return fmaf(2.f, __fdividef(1.f, 1.f + __expf(-2.f * x)), -1.f);
}
__device__ __forceinline__ unsigned int f2tf32(float f) {
    unsigned int r;
    asm("cvt.rna.tf32.f32 %0, %1;" : "=r"(r) : "f"(f));
    return r;
}
__device__ __forceinline__ void mma_tf32(float* d,
    unsigned int a0, unsigned int a1, unsigned int a2, unsigned int a3,
    unsigned int b0, unsigned int b1) {
    asm volatile(
        "mma.sync.aligned.m16n8k8.row.col.f32.tf32.tf32.f32 "
        "{%0,%1,%2,%3}, {%4,%5,%6,%7}, {%8,%9}, {%0,%1,%2,%3};"
        : "+f"(d[0]), "+f"(d[1]), "+f"(d[2]), "+f"(d[3])
        : "r"(a0), "r"(a1), "r"(a2), "r"(a3), "r"(b0), "r"(b1));
}
__device__ __forceinline__ int dr4(int k) {
    return ((k & 3) << 6) | (((k >> 2) & 3) << 4) | (((k >> 4) & 3) << 2) | ((k >> 6) & 3);
}

// ---------------- K1: forward rfft + fused norm-stat partials ----------------
__global__ void __launch_bounds__(512) k_fft_fwd(const float* __restrict__ x) {
    int bc = blockIdx.x;
    int t0 = blockIdx.y * 32;
    int b = bc >> 4, c = bc & 15;
    __shared__ float sr[258][17], si[258][17];
    __shared__ float2 tw[192];
    int tid = threadIdx.x;
    int w = tid >> 5, l = tid & 31;

    if (tid < 192) {
        float sv, cv;
        __sincosf(-6.28318530717958647692f * (float)tid * (1.f / 256.f), &sv, &cv);
        tw[tid] = make_float2(cv, sv);
    }
    for (int i = tid; i < 8192; i += 512) {
        int f = i >> 5, tt = i & 31;
        float v = x[((size_t)bc * 256 + f) * 512 + t0 + tt];
        if (tt & 1) si[f][tt >> 1] = v; else sr[f][tt >> 1] = v;
    }
    __syncthreads();

    #pragma unroll
    for (int stage = 0; stage < 4; ++stage) {
        int ms = 6 - 2 * stage;
        int m = 1 << ms;
        #pragma unroll
        for (int half = 0; half < 2; ++half) {
            int bfy = l + 32 * half;
            int g = bfy >> ms, p = bfy & (m - 1);
            int base = (g << (ms + 2)) + p;
            int e1 = p << (2 * stage);
            float2 w1 = tw[e1], w2 = tw[2 * e1], w3 = tw[3 * e1];
            float ar = sr[base][w],        ai = si[base][w];
            float br = sr[base + m][w],    bi = si[base + m][w];
            float cr = sr[base + 2*m][w],  ci = si[base + 2*m][w];
            float dr = sr[base + 3*m][w],  di = si[base + 3*m][w];
            float t0r = ar + cr, t0i = ai + ci;
            float t1r = ar - cr, t1i = ai - ci;
            float t2r = br + dr, t2i = bi + di;
            float t3r = br - dr, t3i = bi - di;
            sr[base][w] = t0r + t2r;  si[base][w] = t0i + t2i;
            float u1r = t1r + t3i, u1i = t1i - t3r;
            sr[base + m][w]   = u1r * w1.x - u1i * w1.y;
            si[base + m][w]   = u1r * w1.y + u1i * w1.x;
            float v2r = t0r - t2r, v2i = t0i - t2i;
            sr[base + 2*m][w] = v2r * w2.x - v2i * w2.y;
            si[base + 2*m][w] = v2r * w2.y + v2i * w2.x;
            float u3r = t1r - t3i, u3i = t1i + t3r;
            sr[base + 3*m][w] = u3r * w3.x - u3i * w3.y;
            si[base + 3*m][w] = u3r * w3.y + u3i * w3.x;
        }
        __syncwarp();
    }

    float va[5][4];
    #pragma unroll
    for (int r = 0; r < 4; ++r) {
        int k = l + 32 * r;
        int ik = dr4(k), im = dr4((256 - k) & 255);
        float zkr = sr[ik][w], zki = si[ik][w];
        float zmr = sr[im][w], zmi = si[im][w];
        va[r][0] = 0.5f * (zkr + zmr);
        va[r][1] = 0.5f * (zki - zmi);
        va[r][2] = 0.5f * (zki + zmi);
        va[r][3] = 0.5f * (zmr - zkr);
    }
    if (l == 0) {
        int ik = dr4(128);
        float zkr = sr[ik][w], zki = si[ik][w];
        va[4][0] = zkr; va[4][1] = 0.f;
        va[4][2] = zki; va[4][3] = 0.f;
    }

    {
        float sA = 0.f, qA = 0.f, sB = 0.f, qB = 0.f;
        #pragma unroll
        for (int r = 0; r < 4; ++r) {
            sA += va[r][0] + va[r][1];
            qA = fmaf(va[r][0], va[r][0], qA); qA = fmaf(va[r][1], va[r][1], qA);
            sB += va[r][2] + va[r][3];
            qB = fmaf(va[r][2], va[r][2], qB); qB = fmaf(va[r][3], va[r][3], qB);
        }
        if (l == 0) {
            sA += va[4][0] + va[4][1];
            qA = fmaf(va[4][0], va[4][0], qA); qA = fmaf(va[4][1], va[4][1], qA);
            sB += va[4][2] + va[4][3];
            qB = fmaf(va[4][2], va[4][2], qB); qB = fmaf(va[4][3], va[4][3], qB);
        }
        #pragma unroll
        for (int off = 16; off; off >>= 1) {
            sA += __shfl_xor_sync(0xffffffffu, sA, off);
            qA += __shfl_xor_sync(0xffffffffu, qA, off);
            sB += __shfl_xor_sync(0xffffffffu, sB, off);
            qB += __shfl_xor_sync(0xffffffffu, qB, off);
        }
        if (l == 0) {
            int nA = b * 512 + t0 + 2 * w;
            g_psum[nA * 16 + c] = sA;       g_psq[nA * 16 + c] = qA;
            g_psum[(nA + 1) * 16 + c] = sB; g_psq[(nA + 1) * 16 + c] = qB;
        }
    }

    __syncwarp();
    #pragma unroll
    for (int r = 0; r < 4; ++r) {
        int k = l + 32 * r;
        sr[k][w] = va[r][0];        si[k][w] = va[r][1];
        sr[129 + k][w] = va[r][2];  si[129 + k][w] = va[r][3];
    }
    if (l == 0) {
        sr[128][w] = va[4][0];       si[128][w] = va[4][1];
        sr[129 + 128][w] = va[4][2]; si[129 + 128][w] = va[4][3];
    }
    __syncthreads();

    for (int i = tid; i < 4128; i += 512) {
        int k = i >> 5, tt = i & 31;
        int j = tt >> 1;
        int row = (tt & 1) ? (129 + k) : k;
        g_zraw[(((size_t)b * 32 + c)      * 129 + k) * 512 + t0 + tt] = sr[row][j];
        g_zraw[(((size_t)b * 32 + 16 + c) * 129 + k) * 512 + t0 + tt] = si[row][j];
    }
}

// ---------------- K2: finalize stats ----------------------------------------
__global__ void k_stats2() {
    int n = blockIdx.x * 256 + threadIdx.x;
    float S = 0.f, Q = 0.f;
    #pragma unroll
    for (int p = 0; p < 16; ++p) { S += g_psum[n * 16 + p]; Q += g_psq[n * 16 + p]; }
    float mean = S * (1.f / 4128.f);
    float var = (Q - S * mean) * (1.f / 4127.f);
    g_mean[n] = mean;
    g_rstd[n] = __fdividef(1.f, sqrtf(fmaxf(var, 0.f)) + 1e-8f);
}

// ---------------- K3: normalize + gate GEMM (tf32 mma), fp16 permuted out ---
// Gate permutation per dir: position n (0..63) -> weight row (n&1)*32 + (n>>1).
__global__ void __launch_bounds__(256) k_gates(
    const float* __restrict__ nw, const float* __restrict__ nb,
    const float* __restrict__ wihf, const float* __restrict__ bihf, const float* __restrict__ bhhf,
    const float* __restrict__ wihb, const float* __restrict__ bihb, const float* __restrict__ bhhb) {
    int k = blockIdx.x;
    int n0 = blockIdx.y * 64;
    int b = n0 >> 9, tl0 = n0 & 511;
    __shared__ unsigned int ys[32][72];
    __shared__ unsigned int ws[128][36];
    __shared__ float nws[32], nbs[32], means[64], rstds[64], bs[128];
    int tid = threadIdx.x;

    for (int i = tid; i < 2048; i += 256) {
        int c2 = i >> 6, tt = i & 63;
        ys[c2][tt] = __float_as_uint(g_zraw[(((size_t)b * 32 + c2) * 129 + k) * 512 + tl0 + tt]);
    }
    for (int i = tid; i < 4096; i += 256) {
        int n = i >> 5, q = i & 31;
        int dir = n >> 6, nn = n & 63;
        int row = ((nn & 1) << 5) + (nn >> 1);
        float wv = dir ? wihb[row * 32 + q] : wihf[row * 32 + q];
        ws[n][q] = f2tf32(wv);
    }
    if (tid < 128) {
        int dir = tid >> 6, nn = tid & 63;
        int row = ((nn & 1) << 5) + (nn >> 1);
        bs[tid] = dir ? (bihb[row] + bhhb[row]) : (bihf[row] + bhhf[row]);
    }
    if (tid < 32) { nws[tid] = nw[tid * 129 + k]; nbs[tid] = nb[tid * 129 + k]; }
    if (tid >= 128 && tid < 192) { means[tid - 128] = g_mean[n0 + tid - 128]; rstds[tid - 128] = g_rstd[n0 + tid - 128]; }
    __syncthreads();

    for (int i = tid; i < 2048; i += 256) {
        int c2 = i >> 6, tt = i & 63;
        float v = (__uint_as_float(ys[c2][tt]) - means[tt]) * rstds[tt] * nws[c2] + nbs[c2];
        ys[c2][tt] = f2tf32(v);
    }
    __syncthreads();

    int wid = tid >> 5, lane = tid & 31;
    int gid = lane >> 2, tid4 = lane & 3;
    int m_base = (wid & 3) << 4;
    int n_base0 = (wid >> 2) << 6;

    float acc[8][4];
    #pragma unroll
    for (int j = 0; j < 8; ++j) {
        int gb = n_base0 + j * 8 + tid4 * 2;
        acc[j][0] = bs[gb];     acc[j][1] = bs[gb + 1];
        acc[j][2] = bs[gb];     acc[j][3] = bs[gb + 1];
    }

    #pragma unroll
    for (int ks = 0; ks < 32; ks += 8) {
        unsigned int a0 = ys[ks + tid4    ][m_base + gid];
        unsigned int a1 = ys[ks + tid4    ][m_base + gid + 8];
        unsigned int a2 = ys[ks + tid4 + 4][m_base + gid];
        unsigned int a3 = ys[ks + tid4 + 4][m_base + gid + 8];
        #pragma unroll
        for (int j = 0; j < 8; ++j) {
            int gb = n_base0 + j * 8 + gid;
            unsigned int b0 = ws[gb][ks + tid4];
            unsigned int b1 = ws[gb][ks + tid4 + 4];
            mma_tf32(acc[j], a0, a1, a2, a3, b0, b1);
        }
    }

    #pragma unroll
    for (int j = 0; j < 8; ++j) {
        int pos = n_base0 + j * 8 + tid4 * 2;
        int trow = n0 + m_base + gid;
        __half2 v0 = __floats2half2_rn(acc[j][0], acc[j][1]);
        __half2 v1 = __floats2half2_rn(acc[j][2], acc[j][3]);
        *reinterpret_cast<__half2*>(&g_pre16[((size_t)trow * 129 + k) * 128 + pos]) = v0;
        *reinterpret_cast<__half2*>(&g_pre16[((size_t)(trow + 8) * 129 + k) * 128 + pos]) = v1;
    }
}

// ---------------- K4: recurrent-only LSTM, half2 preact loads ---------------
__global__ void __launch_bounds__(256) k_lstm(
    const float* __restrict__ whhf, const float* __restrict__ whhb) {
    int wg = blockIdx.x * 8 + (threadIdx.x >> 5);
    int lane = threadIdx.x & 31;
    int n = wg >> 1, dir = wg & 1;

    const float* whh = dir ? whhb : whhf;
    float wh0[16], wh1[16];
    #pragma unroll
    for (int q = 0; q < 16; ++q) {
        wh0[q] = whh[lane * 16 + q];
        wh1[q] = whh[(lane + 32) * 16 + q];
    }
    float m2 = (lane < 16) ? 2.f : 1.f;
    float mb = (lane < 16) ? -1.f : 0.f;

    // half2 view: lane loads pair at index k*64 + dir*32 + lane
    const __half2* pbase2 = reinterpret_cast<const __half2*>(g_pre16 + (size_t)n * 129 * 128) + dir * 32 + lane;
    float* hbase = g_h + (size_t)n * 129 * 32 + dir * 16;

    float h = 0.f, cst = 0.f;
    int k = dir ? 128 : 0;
    int stepd = dir ? -1 : 1;
    float2 p = __half22float2(pbase2[k * 64]);

    #pragma unroll 2
    for (int s = 0; s < 129; ++s) {
        int kn = k + stepd;
        float2 np = make_float2(0.f, 0.f);
        if (s < 128) np = __half22float2(pbase2[kn * 64]);
        float a0 = p.x, a1 = p.y, c0 = 0.f, c1 = 0.f;
        #pragma unroll
        for (int q = 0; q < 8; ++q) {
            float hv = __shfl_sync(0xffffffffu, h, q);
            a0 = fmaf(hv, wh0[q], a0);
            a1 = fmaf(hv, wh1[q], a1);
        }
        #pragma unroll
        for (int q = 8; q < 16; ++q) {
            float hv = __shfl_sync(0xffffffffu, h, q);
            c0 = fmaf(hv, wh0[q], c0);
            c1 = fmaf(hv, wh1[q], c1);
        }
        a0 += c0; a1 += c1;
        float act0 = sigf(a0);
        float r1 = __fdividef(1.f, 1.f + __expf(-m2 * a1));
        float act1 = fmaf(m2, r1, mb);
        float fa = __shfl_xor_sync(0xffffffffu, act0, 16);
        float oa = __shfl_xor_sync(0xffffffffu, act1, 16);
        if (lane < 16) {
            cst = fmaf(fa, cst, act0 * act1);
            h = oa * tanhfast(cst);
            hbase[k * 32 + lane] = h;
        }
        p = np; k = kn;
    }
}

// ---------------- K5: linear(2H->2C) + complex multiply, retiled ------------
// grid (129, 8, 8): k, 64-t block, b. 256 threads. Transposed smem operands.
__global__ void __launch_bounds__(256) k_lin_cmul(const float* __restrict__ lw, const float* __restrict__ lb) {
    int k = blockIdx.x, t0 = blockIdx.y * 64, b = blockIdx.z;
    __shared__ __align__(16) float hs[32][68];     // [j][t]
    __shared__ __align__(16) float lws[32][34];    // [j][c2]
    __shared__ float lbs[32];
    __shared__ float yls[32][68];                  // [c2][t]
    int tid = threadIdx.x;

    for (int i = tid; i < 2048; i += 256) {
        int tt = i >> 5, j = i & 31;
        hs[j][tt] = g_h[(((size_t)(b * 512 + t0 + tt)) * 129 + k) * 32 + j];
    }
    for (int i = tid; i < 1024; i += 256) {
        int c2 = i >> 5, j = i & 31;
        lws[j][c2] = lw[c2 * 32 + j];
    }
    if (tid < 32) lbs[tid] = lb[tid];
    __syncthreads();

    // GEMM: thread tile 4t x 2c2
    int tg = tid & 15, cg = tid >> 4;
    int t4 = tg << 2, c22 = cg << 1;
    float acc[2][4];
    #pragma unroll
    for (int t = 0; t < 4; ++t) { acc[0][t] = lbs[c22]; acc[1][t] = lbs[c22 + 1]; }
    #pragma unroll 4
    for (int j = 0; j < 32; ++j) {
        float4 hv = *reinterpret_cast<const float4*>(&hs[j][t4]);
        float2 wv = *reinterpret_cast<const float2*>(&lws[j][c22]);
        acc[0][0] = fmaf(hv.x, wv.x, acc[0][0]);
        acc[0][1] = fmaf(hv.y, wv.x, acc[0][1]);
        acc[0][2] = fmaf(hv.z, wv.x, acc[0][2]);
        acc[0][3] = fmaf(hv.w, wv.x, acc[0][3]);
        acc[1][0] = fmaf(hv.x, wv.y, acc[1][0]);
        acc[1][1] = fmaf(hv.y, wv.y, acc[1][1]);
        acc[1][2] = fmaf(hv.z, wv.y, acc[1][2]);
        acc[1][3] = fmaf(hv.w, wv.y, acc[1][3]);
    }
    #pragma unroll
    for (int t = 0; t < 4; ++t) {
        yls[c22][t4 + t] = acc[0][t];
        yls[c22 + 1][t4 + t] = acc[1][t];
    }
    __syncthreads();

    // cmul phase: tt = tid&63, 4 groups of 8 c2
    int tt = tid & 63, g = tid >> 6;
    size_t basez = ((size_t)(b * 32) * 129 + k) * 512 + t0 + tt;
    const size_t ps = (size_t)129 * 512;
    #pragma unroll
    for (int ci = 0; ci < 8; ++ci) {
        int c2 = g * 8 + ci;
        if (c2 < 16) {
            float xr = g_zraw[basez + (size_t)c2 * ps];
            float xi = g_zraw[basez + (size_t)(c2 + 16) * ps];
            float yr = yls[c2][tt], yi = yls[c2 + 16][tt];
            g_P[basez + (size_t)c2 * ps] = yr * xr - yi * xi;
        } else {
            int c = c2 - 16;
            float xr = g_zraw[basez + (size_t)c * ps];
            float xi = g_zraw[basez + (size_t)c2 * ps];
            float yr = yls[c][tt], yi = yls[c2][tt];
            g_P[basez + (size_t)c2 * ps] = yr * xi + yi * xr;
        }
    }
}

// ---------------- K6: irfft, warp-private radix-4, spectrum-pair packed -----
__global__ void __launch_bounds__(512) k_fft_inv(float* __restrict__ out) {
    int bc = blockIdx.x;
    int t0 = blockIdx.y * 32;
    int b = bc >> 4, c = bc & 15;
    __shared__ float sr[258][17], si[258][17];
    __shared__ float2 tw[192];
    int tid = threadIdx.x;
    int w = tid >> 5, l = tid & 31;

    if (tid < 192) {
        float sv, cv;
        __sincosf(6.28318530717958647692f * (float)tid * (1.f / 256.f), &sv, &cv);
        tw[tid] = make_float2(cv, sv);
    }
    for (int i = tid; i < 4128; i += 512) {
        int k = i >> 5, tt = i & 31;
        int j = tt >> 1;
        int row = (tt & 1) ? (129 + k) : k;
        sr[row][j] = g_P[(((size_t)b * 32 + c)      * 129 + k) * 512 + t0 + tt];
        si[row][j] = g_P[(((size_t)b * 32 + 16 + c) * 129 + k) * 512 + t0 + tt];
    }
    __syncthreads();

    float vz[8][2];
    #pragma unroll
    for (int r = 0; r < 8; ++r) {
        int row = l + 32 * r;
        float zr, zi;
        if (row <= 128) {
            float par = sr[row][w];
            float pai = (row == 0 || row == 128) ? 0.f : si[row][w];
            float pbr = sr[129 + row][w];
            float pbi = (row == 0 || row == 128) ? 0.f : si[129 + row][w];
            zr = par - pbi; zi = pai + pbr;
        } else {
            int m = 256 - row;
            float par = sr[m][w], pai = si[m][w];
            float pbr = sr[129 + m][w], pbi = si[129 + m][w];
            zr = par + pbi; zi = pbr - pai;
        }
        vz[r][0] = zr; vz[r][1] = zi;
    }
    __syncwarp();
    #pragma unroll
    for (int r = 0; r < 8; ++r) {
        int row = l + 32 * r;
        sr[row][w] = vz[r][0];
        si[row][w] = vz[r][1];
    }
    __syncwarp();

    #pragma unroll
    for (int stage = 0; stage < 4; ++stage) {
        int ms = 6 - 2 * stage;
        int m = 1 << ms;
        #pragma unroll
        for (int half = 0; half < 2; ++half) {
            int bfy = l + 32 * half;
            int g = bfy >> ms, p = bfy & (m - 1);
            int base = (g << (ms + 2)) + p;
            int e1 = p << (2 * stage);
            float2 w1 = tw[e1], w2 = tw[2 * e1], w3 = tw[3 * e1];
            float ar = sr[base][w],        ai = si[base][w];
            float br = sr[base + m][w],    bi = si[base + m][w];
            float cr = sr[base + 2*m][w],  ci = si[base + 2*m][w];
            float dr = sr[base + 3*m][w],  di = si[base + 3*m][w];
            float t0r = ar + cr, t0i = ai + ci;
            float t1r = ar - cr, t1i = ai - ci;
            float t2r = br + dr, t2i = bi + di;
            float t3r = br - dr, t3i = bi - di;
            sr[base][w] = t0r + t2r;  si[base][w] = t0i + t2i;
            float u1r = t1r - t3i, u1i = t1i + t3r;
            sr[base + m][w]   = u1r * w1.x - u1i * w1.y;
            si[base + m][w]   = u1r * w1.y + u1i * w1.x;
            float v2r = t0r - t2r, v2i = t0i - t2i;
            sr[base + 2*m][w] = v2r * w2.x - v2i * w2.y;
            si[base + 2*m][w] = v2r * w2.y + v2i * w2.x;
            float u3r = t1r + t3i, u3i = t1i - t3r;
            sr[base + 3*m][w] = u3r * w3.x - u3i * w3.y;
            si[base + 3*m][w] = u3r * w3.y + u3i * w3.x;
        }
        __syncwarp();
    }
    __syncthreads();

    const float inv = 1.f / 256.f;
    for (int i = tid; i < 8192; i += 512) {
        int f = i >> 5, tt = i & 31;
        int j = tt >> 1;
        int src = dr4(f);
        float v = (tt & 1) ? si[src][j] : sr[src][j];
        out[((size_t)bc * 256 + f) * 512 + t0 + tt] = v * inv;
    }
}

// ---------------- launcher ---------------------------------------------------
extern "C" void kernel_launch(void* const* d_in, const int* in_sizes, int n_in,
                              void* d_out, int out_size) {
    const float* x    = (const float*)d_in[0];
    const float* nw   = (const float*)d_in[1];
    const float* nb   = (const float*)d_in[2];
    const float* wihf = (const float*)d_in[3];
    const float* whhf = (const float*)d_in[4];
    const float* bihf = (const float*)d_in[5];
    const float* bhhf = (const float*)d_in[6];
    const float* wihb = (const float*)d_in[7];
    const float* whhb = (const float*)d_in[8];
    const float* bihb = (const float*)d_in[9];
    const float* bhhb = (const float*)d_in[10];
    const float* lw   = (const float*)d_in[11];
    const float* lb   = (const float*)d_in[12];
    float* out = (float*)d_out;

    k_fft_fwd<<<dim3(128, 16), 512>>>(x);
    k_stats2<<<16, 256>>>();
    k_gates<<<dim3(129, 64), 256>>>(nw, nb, wihf, bihf, bhhf, wihb, bihb, bhhb);
    k_lstm<<<1024, 256>>>(whhf, whhb);
    k_lin_cmul<<<dim3(129, 8, 8), 256>>>(lw, lb);
    k_fft_inv<<<dim3(128, 16), 512>>>(out);
}

// round 16
// speedup vs baseline: 1.3160x; 1.1209x over previous
#include <cuda_runtime.h>
#include <cuda_fp16.h>
#include <cstdint>

#define BB 8
#define CC 16
#define FDIM 256
#define F2 129
#define TT 512
#define C2 32
#define HH 16
#define NT (BB*TT)

// ---------------- device scratch ----------------
__device__ float g_zraw[(size_t)BB*C2*F2*TT];   // spectrum planes (b, c2, k, t): re c=0..15, im c=16..31
__device__ __half g_pre16[(size_t)NT*F2*128];   // fp16 gate preacts, PERMUTED: pos 2m/2m+1 = rows m/m+32 per dir
__device__ float g_h   [(size_t)NT*F2*C2];      // LSTM hidden cat(fwd,bwd): (n, k, 2H)
__device__ float4 g_P4 [(size_t)BB*16*F2*256];  // packed product spectra: (b,c,k,tpair) = (zr,zi,wr,wi)
__device__ float g_mean[NT];
__device__ float g_rstd[NT];
__device__ float g_psum[NT*16];
__device__ float g_psq [NT*16];

__device__ __forceinline__ float sigf(float x) {
    return __fdividef(1.f, 1.f + __expf(-x));
}
__device__ __forceinline__ float tanhfast(float x) {
    return fmaf(2.f, __fdividef(1.f, 1.f + __expf(-2.f * x)), -1.f);
}
__device__ __forceinline__ unsigned int f2tf32(float f) {
    unsigned int r;
    asm("cvt.rna.tf32.f32 %0, %1;" : "=r"(r) : "f"(f));
    return r;
}
__device__ __forceinline__ void mma_tf32(float* d,
    unsigned int a0, unsigned int a1, unsigned int a2, unsigned int a3,
    unsigned int b0, unsigned int b1) {
    asm volatile(
        "mma.sync.aligned.m16n8k8.row.col.f32.tf32.tf32.f32 "
        "{%0,%1,%2,%3}, {%4,%5,%6,%7}, {%8,%9}, {%0,%1,%2,%3};"
        : "+f"(d[0]), "+f"(d[1]), "+f"(d[2]), "+f"(d[3])
        : "r"(a0), "r"(a1), "r"(a2), "r"(a3), "r"(b0), "r"(b1));
}
__device__ __forceinline__ int dr4(int k) {
    return ((k & 3) << 6) | (((k >> 2) & 3) << 4) | (((k >> 4) & 3) << 2) | ((k >> 6) & 3);
}

// ---------------- K1: forward rfft + fused norm-stat partials ----------------
__global__ void __launch_bounds__(512) k_fft_fwd(const float* __restrict__ x) {
    int bc = blockIdx.x;
    int t0 = blockIdx.y * 32;
    int b = bc >> 4, c = bc & 15;
    __shared__ float sr[258][17], si[258][17];
    __shared__ float2 tw[192];
    int tid = threadIdx.x;
    int w = tid >> 5, l = tid & 31;

    if (tid < 192) {
        float sv, cv;
        __sincosf(-6.28318530717958647692f * (float)tid * (1.f / 256.f), &sv, &cv);
        tw[tid] = make_float2(cv, sv);
    }
    for (int i = tid; i < 8192; i += 512) {
        int f = i >> 5, tt = i & 31;
        float v = x[((size_t)bc * 256 + f) * 512 + t0 + tt];
        if (tt & 1) si[f][tt >> 1] = v; else sr[f][tt >> 1] = v;
    }
    __syncthreads();

    #pragma unroll
    for (int stage = 0; stage < 4; ++stage) {
        int ms = 6 - 2 * stage;
        int m = 1 << ms;
        #pragma unroll
        for (int half = 0; half < 2; ++half) {
            int bfy = l + 32 * half;
            int g = bfy >> ms, p = bfy & (m - 1);
            int base = (g << (ms + 2)) + p;
            int e1 = p << (2 * stage);
            float2 w1 = tw[e1], w2 = tw[2 * e1], w3 = tw[3 * e1];
            float ar = sr[base][w],        ai = si[base][w];
            float br = sr[base + m][w],    bi = si[base + m][w];
            float cr = sr[base + 2*m][w],  ci = si[base + 2*m][w];
            float dr = sr[base + 3*m][w],  di = si[base + 3*m][w];
            float t0r = ar + cr, t0i = ai + ci;
            float t1r = ar - cr, t1i = ai - ci;
            float t2r = br + dr, t2i = bi + di;
            float t3r = br - dr, t3i = bi - di;
            sr[base][w] = t0r + t2r;  si[base][w] = t0i + t2i;
            float u1r = t1r + t3i, u1i = t1i - t3r;
            sr[base + m][w]   = u1r * w1.x - u1i * w1.y;
            si[base + m][w]   = u1r * w1.y + u1i * w1.x;
            float v2r = t0r - t2r, v2i = t0i - t2i;
            sr[base + 2*m][w] = v2r * w2.x - v2i * w2.y;
            si[base + 2*m][w] = v2r * w2.y + v2i * w2.x;
            float u3r = t1r - t3i, u3i = t1i + t3r;
            sr[base + 3*m][w] = u3r * w3.x - u3i * w3.y;
            si[base + 3*m][w] = u3r * w3.y + u3i * w3.x;
        }
        __syncwarp();
    }

    float va[5][4];
    #pragma unroll
    for (int r = 0; r < 4; ++r) {
        int k = l + 32 * r;
        int ik = dr4(k), im = dr4((256 - k) & 255);
        float zkr = sr[ik][w], zki = si[ik][w];
        float zmr = sr[im][w], zmi = si[im][w];
        va[r][0] = 0.5f * (zkr + zmr);
        va[r][1] = 0.5f * (zki - zmi);
        va[r][2] = 0.5f * (zki + zmi);
        va[r][3] = 0.5f * (zmr - zkr);
    }
    if (l == 0) {
        int ik = dr4(128);
        float zkr = sr[ik][w], zki = si[ik][w];
        va[4][0] = zkr; va[4][1] = 0.f;
        va[4][2] = zki; va[4][3] = 0.f;
    }

    {
        float sA = 0.f, qA = 0.f, sB = 0.f, qB = 0.f;
        #pragma unroll
        for (int r = 0; r < 4; ++r) {
            sA += va[r][0] + va[r][1];
            qA = fmaf(va[r][0], va[r][0], qA); qA = fmaf(va[r][1], va[r][1], qA);
            sB += va[r][2] + va[r][3];
            qB = fmaf(va[r][2], va[r][2], qB); qB = fmaf(va[r][3], va[r][3], qB);
        }
        if (l == 0) {
            sA += va[4][0] + va[4][1];
            qA = fmaf(va[4][0], va[4][0], qA); qA = fmaf(va[4][1], va[4][1], qA);
            sB += va[4][2] + va[4][3];
            qB = fmaf(va[4][2], va[4][2], qB); qB = fmaf(va[4][3], va[4][3], qB);
        }
        #pragma unroll
        for (int off = 16; off; off >>= 1) {
            sA += __shfl_xor_sync(0xffffffffu, sA, off);
            qA += __shfl_xor_sync(0xffffffffu, qA, off);
            sB += __shfl_xor_sync(0xffffffffu, sB, off);
            qB += __shfl_xor_sync(0xffffffffu, qB, off);
        }
        if (l == 0) {
            int nA = b * 512 + t0 + 2 * w;
            g_psum[nA * 16 + c] = sA;       g_psq[nA * 16 + c] = qA;
            g_psum[(nA + 1) * 16 + c] = sB; g_psq[(nA + 1) * 16 + c] = qB;
        }
    }

    __syncwarp();
    #pragma unroll
    for (int r = 0; r < 4; ++r) {
        int k = l + 32 * r;
        sr[k][w] = va[r][0];        si[k][w] = va[r][1];
        sr[129 + k][w] = va[r][2];  si[129 + k][w] = va[r][3];
    }
    if (l == 0) {
        sr[128][w] = va[4][0];       si[128][w] = va[4][1];
        sr[129 + 128][w] = va[4][2]; si[129 + 128][w] = va[4][3];
    }
    __syncthreads();

    for (int i = tid; i < 4128; i += 512) {
        int k = i >> 5, tt = i & 31;
        int j = tt >> 1;
        int row = (tt & 1) ? (129 + k) : k;
        g_zraw[(((size_t)b * 32 + c)      * 129 + k) * 512 + t0 + tt] = sr[row][j];
        g_zraw[(((size_t)b * 32 + 16 + c) * 129 + k) * 512 + t0 + tt] = si[row][j];
    }
}

// ---------------- K2: finalize stats ----------------------------------------
__global__ void k_stats2() {
    int n = blockIdx.x * 256 + threadIdx.x;
    float S = 0.f, Q = 0.f;
    #pragma unroll
    for (int p = 0; p < 16; ++p) { S += g_psum[n * 16 + p]; Q += g_psq[n * 16 + p]; }
    float mean = S * (1.f / 4128.f);
    float var = (Q - S * mean) * (1.f / 4127.f);
    g_mean[n] = mean;
    g_rstd[n] = __fdividef(1.f, sqrtf(fmaxf(var, 0.f)) + 1e-8f);
}

// ---------------- K3: normalize + gate GEMM (tf32 mma), staged fp16 out -----
__global__ void __launch_bounds__(256) k_gates(
    const float* __restrict__ nw, const float* __restrict__ nb,
    const float* __restrict__ wihf, const float* __restrict__ bihf, const float* __restrict__ bhhf,
    const float* __restrict__ wihb, const float* __restrict__ bihb, const float* __restrict__ bhhb) {
    int k = blockIdx.x;
    int n0 = blockIdx.y * 64;
    int b = n0 >> 9, tl0 = n0 & 511;
    __shared__ unsigned int ys[32][72];
    __shared__ __align__(16) union {
        unsigned int w[128][36];         // tf32 weight bits (dead after mma)
        __half stage[64][136];           // fp16 output staging (pitch 272B)
    } u;
    __shared__ float nws[32], nbs[32], means[64], rstds[64], bs[128];
    int tid = threadIdx.x;

    for (int i = tid; i < 2048; i += 256) {
        int c2 = i >> 6, tt = i & 63;
        ys[c2][tt] = __float_as_uint(g_zraw[(((size_t)b * 32 + c2) * 129 + k) * 512 + tl0 + tt]);
    }
    for (int i = tid; i < 4096; i += 256) {
        int n = i >> 5, q = i & 31;
        int dir = n >> 6, nn = n & 63;
        int row = ((nn & 1) << 5) + (nn >> 1);
        float wv = dir ? wihb[row * 32 + q] : wihf[row * 32 + q];
        u.w[n][q] = f2tf32(wv);
    }
    if (tid < 128) {
        int dir = tid >> 6, nn = tid & 63;
        int row = ((nn & 1) << 5) + (nn >> 1);
        bs[tid] = dir ? (bihb[row] + bhhb[row]) : (bihf[row] + bhhf[row]);
    }
    if (tid < 32) { nws[tid] = nw[tid * 129 + k]; nbs[tid] = nb[tid * 129 + k]; }
    if (tid >= 128 && tid < 192) { means[tid - 128] = g_mean[n0 + tid - 128]; rstds[tid - 128] = g_rstd[n0 + tid - 128]; }
    __syncthreads();

    for (int i = tid; i < 2048; i += 256) {
        int c2 = i >> 6, tt = i & 63;
        float v = (__uint_as_float(ys[c2][tt]) - means[tt]) * rstds[tt] * nws[c2] + nbs[c2];
        ys[c2][tt] = f2tf32(v);
    }
    __syncthreads();

    int wid = tid >> 5, lane = tid & 31;
    int gid = lane >> 2, tid4 = lane & 3;
    int m_base = (wid & 3) << 4;
    int n_base0 = (wid >> 2) << 6;

    float acc[8][4];
    #pragma unroll
    for (int j = 0; j < 8; ++j) {
        int gb = n_base0 + j * 8 + tid4 * 2;
        acc[j][0] = bs[gb];     acc[j][1] = bs[gb + 1];
        acc[j][2] = bs[gb];     acc[j][3] = bs[gb + 1];
    }

    #pragma unroll
    for (int ks = 0; ks < 32; ks += 8) {
        unsigned int a0 = ys[ks + tid4    ][m_base + gid];
        unsigned int a1 = ys[ks + tid4    ][m_base + gid + 8];
        unsigned int a2 = ys[ks + tid4 + 4][m_base + gid];
        unsigned int a3 = ys[ks + tid4 + 4][m_base + gid + 8];
        #pragma unroll
        for (int j = 0; j < 8; ++j) {
            int gb = n_base0 + j * 8 + gid;
            unsigned int b0 = u.w[gb][ks + tid4];
            unsigned int b1 = u.w[gb][ks + tid4 + 4];
            mma_tf32(acc[j], a0, a1, a2, a3, b0, b1);
        }
    }
    __syncthreads();   // all warps done reading u.w

    // stage fp16 tile
    #pragma unroll
    for (int j = 0; j < 8; ++j) {
        int pos = n_base0 + j * 8 + tid4 * 2;
        int r0 = m_base + gid;
        __half2 v0 = __floats2half2_rn(acc[j][0], acc[j][1]);
        __half2 v1 = __floats2half2_rn(acc[j][2], acc[j][3]);
        *reinterpret_cast<__half2*>(&u.stage[r0][pos]) = v0;
        *reinterpret_cast<__half2*>(&u.stage[r0 + 8][pos]) = v1;
    }
    __syncthreads();

    // coalesced copy-out: 64 rows x 256B
    for (int i = tid; i < 1024; i += 256) {
        int row = i >> 4, q4 = i & 15;
        uint4 v = *reinterpret_cast<const uint4*>(&u.stage[row][q4 * 8]);
        *reinterpret_cast<uint4*>(&g_pre16[((size_t)(n0 + row) * 129 + k) * 128 + q4 * 8]) = v;
    }
}

// ---------------- K4: recurrent-only LSTM, half2 preact loads ---------------
__global__ void __launch_bounds__(256) k_lstm(
    const float* __restrict__ whhf, const float* __restrict__ whhb) {
    int wg = blockIdx.x * 8 + (threadIdx.x >> 5);
    int lane = threadIdx.x & 31;
    int n = wg >> 1, dir = wg & 1;

    const float* whh = dir ? whhb : whhf;
    float wh0[16], wh1[16];
    #pragma unroll
    for (int q = 0; q < 16; ++q) {
        wh0[q] = whh[lane * 16 + q];
        wh1[q] = whh[(lane + 32) * 16 + q];
    }
    float m2 = (lane < 16) ? 2.f : 1.f;
    float mb = (lane < 16) ? -1.f : 0.f;

    const __half2* pbase2 = reinterpret_cast<const __half2*>(g_pre16 + (size_t)n * 129 * 128) + dir * 32 + lane;
    float* hbase = g_h + (size_t)n * 129 * 32 + dir * 16;

    float h = 0.f, cst = 0.f;
    int k = dir ? 128 : 0;
    int stepd = dir ? -1 : 1;
    float2 p = __half22float2(pbase2[k * 64]);

    #pragma unroll 2
    for (int s = 0; s < 129; ++s) {
        int kn = k + stepd;
        float2 np = make_float2(0.f, 0.f);
        if (s < 128) np = __half22float2(pbase2[kn * 64]);
        float a0 = p.x, a1 = p.y, c0 = 0.f, c1 = 0.f;
        #pragma unroll
        for (int q = 0; q < 8; ++q) {
            float hv = __shfl_sync(0xffffffffu, h, q);
            a0 = fmaf(hv, wh0[q], a0);
            a1 = fmaf(hv, wh1[q], a1);
        }
        #pragma unroll
        for (int q = 8; q < 16; ++q) {
            float hv = __shfl_sync(0xffffffffu, h, q);
            c0 = fmaf(hv, wh0[q], c0);
            c1 = fmaf(hv, wh1[q], c1);
        }
        a0 += c0; a1 += c1;
        float act0 = sigf(a0);
        float r1 = __fdividef(1.f, 1.f + __expf(-m2 * a1));
        float act1 = fmaf(m2, r1, mb);
        float fa = __shfl_xor_sync(0xffffffffu, act0, 16);
        float oa = __shfl_xor_sync(0xffffffffu, act1, 16);
        if (lane < 16) {
            cst = fmaf(fa, cst, act0 * act1);
            h = oa * tanhfast(cst);
            hbase[k * 32 + lane] = h;
        }
        p = np; k = kn;
    }
}

// ---------------- K5: linear(2H->2C) + cmul, packed-Z float4 output ---------
// grid (129, 8, 8): k, 64-t block, b. 256 threads.
__global__ void __launch_bounds__(256) k_lin_cmul(const float* __restrict__ lw, const float* __restrict__ lb) {
    int k = blockIdx.x, t0 = blockIdx.y * 64, b = blockIdx.z;
    __shared__ __align__(16) float hs[32][68];     // [j][t]
    __shared__ __align__(16) float lws[32][34];    // [j][c2]
    __shared__ float lbs[32];
    __shared__ __align__(16) float yls[32][68];    // [c2][t]
    int tid = threadIdx.x;

    for (int i = tid; i < 2048; i += 256) {
        int tt = i >> 5, j = i & 31;
        hs[j][tt] = g_h[(((size_t)(b * 512 + t0 + tt)) * 129 + k) * 32 + j];
    }
    for (int i = tid; i < 1024; i += 256) {
        int c2 = i >> 5, j = i & 31;
        lws[j][c2] = lw[c2 * 32 + j];
    }
    if (tid < 32) lbs[tid] = lb[tid];
    __syncthreads();

    int tg = tid & 15, cg = tid >> 4;
    int t4 = tg << 2, c22 = cg << 1;
    float acc[2][4];
    #pragma unroll
    for (int t = 0; t < 4; ++t) { acc[0][t] = lbs[c22]; acc[1][t] = lbs[c22 + 1]; }
    #pragma unroll 4
    for (int j = 0; j < 32; ++j) {
        float4 hv = *reinterpret_cast<const float4*>(&hs[j][t4]);
        float2 wv = *reinterpret_cast<const float2*>(&lws[j][c22]);
        acc[0][0] = fmaf(hv.x, wv.x, acc[0][0]);
        acc[0][1] = fmaf(hv.y, wv.x, acc[0][1]);
        acc[0][2] = fmaf(hv.z, wv.x, acc[0][2]);
        acc[0][3] = fmaf(hv.w, wv.x, acc[0][3]);
        acc[1][0] = fmaf(hv.x, wv.y, acc[1][0]);
        acc[1][1] = fmaf(hv.y, wv.y, acc[1][1]);
        acc[1][2] = fmaf(hv.z, wv.y, acc[1][2]);
        acc[1][3] = fmaf(hv.w, wv.y, acc[1][3]);
    }
    #pragma unroll
    for (int t = 0; t < 4; ++t) {
        yls[c22][t4 + t] = acc[0][t];
        yls[c22 + 1][t4 + t] = acc[1][t];
    }
    __syncthreads();

    // cmul + pack: 16 c x 32 t-pairs = 512 items, 2/thread
    bool edge = (k == 0) | (k == 128);
    for (int i = tid; i < 512; i += 256) {
        int c = i >> 5, tp = i & 31;
        int t2 = tp * 2;
        float2 xr2 = *reinterpret_cast<const float2*>(&g_zraw[(((size_t)b * 32 + c) * 129 + k) * 512 + t0 + t2]);
        float2 xi2 = *reinterpret_cast<const float2*>(&g_zraw[(((size_t)b * 32 + 16 + c) * 129 + k) * 512 + t0 + t2]);
        float2 yr = *reinterpret_cast<const float2*>(&yls[c][t2]);
        float2 yi = *reinterpret_cast<const float2*>(&yls[c + 16][t2]);
        float par = yr.x * xr2.x - yi.x * xi2.x;
        float pai = yr.x * xi2.x + yi.x * xr2.x;
        float pbr = yr.y * xr2.y - yi.y * xi2.y;
        float pbi = yr.y * xi2.y + yi.y * xr2.y;
        if (edge) { pai = 0.f; pbi = 0.f; }
        float4 v = make_float4(par - pbi, pai + pbr, par + pbi, pbr - pai);
        g_P4[((size_t)(b * 16 + c) * 129 + k) * 256 + (t0 >> 1) + tp] = v;
    }
}

// ---------------- K6: irfft from packed-Z float4 (no pack phase) ------------
// grid (128, 16), block 512.
__global__ void __launch_bounds__(512) k_fft_inv(float* __restrict__ out) {
    int bc = blockIdx.x;
    int t0 = blockIdx.y * 32;
    int b = bc >> 4, c = bc & 15;
    __shared__ float sr[258][17], si[258][17];
    __shared__ float2 tw[192];
    int tid = threadIdx.x;
    int w = tid >> 5, l = tid & 31;

    if (tid < 192) {
        float sv, cv;
        __sincosf(6.28318530717958647692f * (float)tid * (1.f / 256.f), &sv, &cv);
        tw[tid] = make_float2(cv, sv);
    }
    // direct packed load: row k gets (zr,zi), row 256-k gets (wr,wi)
    const float4* pb4 = g_P4 + (size_t)(b * 16 + c) * 129 * 256 + (t0 >> 1);
    for (int i = tid; i < 2064; i += 512) {
        int k = i >> 4, j = i & 15;
        float4 v = pb4[(size_t)k * 256 + j];
        sr[k][j] = v.x; si[k][j] = v.y;
        if (k >= 1 && k <= 127) {
            sr[256 - k][j] = v.z; si[256 - k][j] = v.w;
        }
    }
    __syncthreads();

    #pragma unroll
    for (int stage = 0; stage < 4; ++stage) {
        int ms = 6 - 2 * stage;
        int m = 1 << ms;
        #pragma unroll
        for (int half = 0; half < 2; ++half) {
            int bfy = l + 32 * half;
            int g = bfy >> ms, p = bfy & (m - 1);
            int base = (g << (ms + 2)) + p;
            int e1 = p << (2 * stage);
            float2 w1 = tw[e1], w2 = tw[2 * e1], w3 = tw[3 * e1];
            float ar = sr[base][w],        ai = si[base][w];
            float br = sr[base + m][w],    bi = si[base + m][w];
            float cr = sr[base + 2*m][w],  ci = si[base + 2*m][w];
            float dr = sr[base + 3*m][w],  di = si[base + 3*m][w];
            float t0r = ar + cr, t0i = ai + ci;
            float t1r = ar - cr, t1i = ai - ci;
            float t2r = br + dr, t2i = bi + di;
            float t3r = br - dr, t3i = bi - di;
            sr[base][w] = t0r + t2r;  si[base][w] = t0i + t2i;
            float u1r = t1r - t3i, u1i = t1i + t3r;
            sr[base + m][w]   = u1r * w1.x - u1i * w1.y;
            si[base + m][w]   = u1r * w1.y + u1i * w1.x;
            float v2r = t0r - t2r, v2i = t0i - t2i;
            sr[base + 2*m][w] = v2r * w2.x - v2i * w2.y;
            si[base + 2*m][w] = v2r * w2.y + v2i * w2.x;
            float u3r = t1r + t3i, u3i = t1i - t3r;
            sr[base + 3*m][w] = u3r * w3.x - u3i * w3.y;
            si[base + 3*m][w] = u3r * w3.y + u3i * w3.x;
        }
        __syncwarp();
    }
    __syncthreads();

    const float inv = 1.f / 256.f;
    for (int i = tid; i < 8192; i += 512) {
        int f = i >> 5, tt = i & 31;
        int j = tt >> 1;
        int src = dr4(f);
        float v = (tt & 1) ? si[src][j] : sr[src][j];
        out[((size_t)bc * 256 + f) * 512 + t0 + tt] = v * inv;
    }
}

// ---------------- launcher ---------------------------------------------------
extern "C" void kernel_launch(void* const* d_in, const int* in_sizes, int n_in,
                              void* d_out, int out_size) {
    const float* x    = (const float*)d_in[0];
    const float* nw   = (const float*)d_in[1];
    const float* nb   = (const float*)d_in[2];
    const float* wihf = (const float*)d_in[3];
    const float* whhf = (const float*)d_in[4];
    const float* bihf = (const float*)d_in[5];
    const float* bhhf = (const float*)d_in[6];
    const float* wihb = (const float*)d_in[7];
    const float* whhb = (const float*)d_in[8];
    const float* bihb = (const float*)d_in[9];
    const float* bhhb = (const float*)d_in[10];
    const float* lw   = (const float*)d_in[11];
    const float* lb   = (const float*)d_in[12];
    float* out = (float*)d_out;

    k_fft_fwd<<<dim3(128, 16), 512>>>(x);
    k_stats2<<<16, 256>>>();
    k_gates<<<dim3(129, 64), 256>>>(nw, nb, wihf, bihf, bhhf, wihb, bihb, bhhb);
    k_lstm<<<1024, 256>>>(whhf, whhb);
    k_lin_cmul<<<dim3(129, 8, 8), 256>>>(lw, lb);
    k_fft_inv<<<dim3(128, 16), 512>>>(out);
}